// round 1
// baseline (speedup 1.0000x reference)
#include <cuda_runtime.h>

#define TPB 256

constexpr int B_     = 16384;
constexpr int N_     = 70;
constexpr int E_     = 3;
constexpr int S_     = 10;
constexpr int NE_    = 210;   // E_*N_
constexpr int STEPS_ = 5;
constexpr int BB_    = 16;            // batch elements per CTA
constexpr int COLS_  = BB_ * S_;      // 160 scalar columns of the big GEMM
constexpr int PAIRS_ = COLS_ / 2;     // 80 f32x2 columns
constexpr int PSTR_  = 11;            // padded prop row stride (conflict-free)

// ---- shared memory layout (float offsets) ----
constexpr int OFF_A   = 0;                      // 80*210 = 16800 (rows 70..79 zero)
constexpr int OFF_X   = OFF_A + 80 * NE_;       // X / a_in buffer: 70*160 = 11200
constexpr int OFF_P   = OFF_X + N_ * COLS_;     // prop: 16*70*11 = 12320
constexpr int OFF_ANN = OFF_P + BB_ * N_ * PSTR_; // 1120
constexpr int OFF_WIN = OFF_ANN + BB_ * N_;     // 300
constexpr int OFF_BIN = OFF_WIN + 300;          // 30
constexpr int OFF_WR  = OFF_BIN + 30;           // 200
constexpr int OFF_BR  = OFF_WR + 200;           // 10
constexpr int OFF_WZ  = OFF_BR + 10;            // 200
constexpr int OFF_BZ  = OFF_WZ + 200;           // 10
constexpr int OFF_WH  = OFF_BZ + 10;            // 200
constexpr int OFF_BH  = OFF_WH + 200;           // 10
constexpr int OFF_WO1 = OFF_BH + 10;            // 110
constexpr int OFF_BO1 = OFF_WO1 + 110;          // 10
constexpr int OFF_WO2 = OFF_BO1 + 10;           // 10
constexpr int OFF_BO2 = OFF_WO2 + 10;           // 1
constexpr int SMEM_FLOATS = OFF_BO2 + 1;        // 42531 -> 170124 bytes

// ---- packed f32x2 helpers (Blackwell) ----
__device__ __forceinline__ unsigned long long ffma2(unsigned long long a,
                                                    unsigned long long b,
                                                    unsigned long long c) {
    unsigned long long d;
    asm("fma.rn.f32x2 %0, %1, %2, %3;" : "=l"(d) : "l"(a), "l"(b), "l"(c));
    return d;
}
__device__ __forceinline__ unsigned long long pack2(float x) {
    unsigned long long d;
    asm("mov.b64 %0, {%1, %1};" : "=l"(d) : "f"(x));
    return d;
}

__device__ __forceinline__ float sigf(float x) {
    return __fdividef(1.0f, 1.0f + __expf(-x));
}
__device__ __forceinline__ float tanh_(float x) {
    float e = __expf(-2.0f * x);
    return __fdividef(1.0f - e, 1.0f + e);
}

extern __shared__ float sm[];

__global__ void __launch_bounds__(TPB, 1) ggnn_kernel(
    const float* __restrict__ annotation, const float* __restrict__ A,
    const float* __restrict__ W_in, const float* __restrict__ b_in,
    const float* __restrict__ Wr, const float* __restrict__ br,
    const float* __restrict__ Wz, const float* __restrict__ bz,
    const float* __restrict__ Wh, const float* __restrict__ bh,
    const float* __restrict__ Wo1, const float* __restrict__ bo1,
    const float* __restrict__ Wo2, const float* __restrict__ bo2,
    float* __restrict__ out)
{
    const int t  = threadIdx.x;
    const int b0 = blockIdx.x * BB_;

    // ---- stage weights + A into SMEM ----
    for (int i = t; i < N_ * NE_; i += TPB) sm[OFF_A + i] = A[i];
    for (int i = t; i < 10 * NE_; i += TPB) sm[OFF_A + N_ * NE_ + i] = 0.0f; // pad rows
    for (int i = t; i < 300; i += TPB) sm[OFF_WIN + i] = W_in[i];
    if (t < 30) sm[OFF_BIN + t] = b_in[t];
    for (int i = t; i < 200; i += TPB) sm[OFF_WR + i] = Wr[i];
    if (t < 10) sm[OFF_BR + t] = br[t];
    for (int i = t; i < 200; i += TPB) sm[OFF_WZ + i] = Wz[i];
    if (t < 10) sm[OFF_BZ + t] = bz[t];
    for (int i = t; i < 200; i += TPB) sm[OFF_WH + i] = Wh[i];
    if (t < 10) sm[OFF_BH + t] = bh[t];
    for (int i = t; i < 110; i += TPB) sm[OFF_WO1 + i] = Wo1[i];
    if (t < 10) sm[OFF_BO1 + t] = bo1[t];
    if (t < 10) sm[OFF_WO2 + t] = Wo2[t];
    if (t == 0) sm[OFF_BO2] = bo2[0];

    // ---- annotation load + prop init: prop[:, :, 0] = ann, rest zero ----
    for (int i = t; i < BB_ * N_; i += TPB) {
        int bb = i / N_, n = i % N_;
        float a = annotation[(b0 + bb) * N_ + n];
        sm[OFF_ANN + i] = a;
        float* pr = sm + OFF_P + (bb * N_ + n) * PSTR_;
        pr[0] = a;
#pragma unroll
        for (int d = 1; d < S_; ++d) pr[d] = 0.0f;
    }
    __syncthreads();

    const int tx = t & 15;   // f32x2 column group (16)
    const int ty = t >> 4;   // row group (16)

    unsigned long long acc[5][5];

#pragma unroll 1
    for (int step = 0; step < STEPS_; ++step) {
#pragma unroll
        for (int i = 0; i < 5; ++i)
#pragma unroll
            for (int j = 0; j < 5; ++j) acc[i][j] = 0ull;

#pragma unroll 1
        for (int e = 0; e < E_; ++e) {
            // ---- build X[n', bb*10+s] = ins for edge e (tasks: (n, bbg of 2 batches)) ----
#pragma unroll 1
            for (int task = t; task < 8 * N_; task += TPB) {
                int n = task >> 3;
                int bb0 = (task & 7) * 2;
                float pv[2][10];
#pragma unroll
                for (int q = 0; q < 2; ++q) {
                    const float* pr = sm + OFF_P + ((bb0 + q) * N_ + n) * PSTR_;
#pragma unroll
                    for (int d = 0; d < 10; ++d) pv[q][d] = pr[d];
                }
#pragma unroll 2
                for (int s = 0; s < 10; ++s) {
                    float base = sm[OFF_BIN + e * S_ + s];
                    float a0 = base, a1 = base;
#pragma unroll
                    for (int d = 0; d < 10; ++d) {
                        float w = sm[OFF_WIN + (e * S_ + s) * S_ + d];
                        a0 += pv[0][d] * w;
                        a1 += pv[1][d] * w;
                    }
                    sm[OFF_X + n * COLS_ + (bb0 + 0) * S_ + s] = a0;
                    sm[OFF_X + n * COLS_ + (bb0 + 1) * S_ + s] = a1;
                }
            }
            __syncthreads();

            // ---- partial GEMM: acc += A[:, e*70 : e*70+70] @ X ----
            {
                const float* pa0 = sm + OFF_A + (ty + 0)  * NE_ + e * 70;
                const float* pa1 = sm + OFF_A + (ty + 16) * NE_ + e * 70;
                const float* pa2 = sm + OFF_A + (ty + 32) * NE_ + e * 70;
                const float* pa3 = sm + OFF_A + (ty + 48) * NE_ + e * 70;
                const float* pa4 = sm + OFF_A + (ty + 64) * NE_ + e * 70;
                const unsigned long long* x2 =
                    (const unsigned long long*)(sm + OFF_X);
#pragma unroll 5
                for (int k = 0; k < 70; ++k) {
                    unsigned long long av2[5];
                    av2[0] = pack2(pa0[k]);
                    av2[1] = pack2(pa1[k]);
                    av2[2] = pack2(pa2[k]);
                    av2[3] = pack2(pa3[k]);
                    av2[4] = pack2(pa4[k]);
                    unsigned long long xv[5];
#pragma unroll
                    for (int j = 0; j < 5; ++j)
                        xv[j] = x2[k * PAIRS_ + tx + 16 * j];
#pragma unroll
                    for (int i = 0; i < 5; ++i)
#pragma unroll
                        for (int j = 0; j < 5; ++j)
                            acc[i][j] = ffma2(av2[i], xv[j], acc[i][j]);
                }
            }
            __syncthreads();
        }

        // ---- write a_in into the X buffer (aliased) ----
#pragma unroll
        for (int i = 0; i < 5; ++i) {
            int n = ty + 16 * i;
            if (n < N_) {
#pragma unroll
                for (int j = 0; j < 5; ++j) {
                    *(unsigned long long*)(sm + OFF_X + n * COLS_ +
                                           2 * (tx + 16 * j)) = acc[i][j];
                }
            }
        }
        __syncthreads();

        // ---- gates: r, z, h_hat, prop update (tasks: (n, bbg of 2 batches)) ----
#pragma unroll 1
        for (int task = t; task < 8 * N_; task += TPB) {
            int n = task >> 3;
            int bb0 = (task & 7) * 2;
            float pv[2][10], av[2][10], rp[2][10];
#pragma unroll
            for (int q = 0; q < 2; ++q) {
                const float* pr = sm + OFF_P + ((bb0 + q) * N_ + n) * PSTR_;
                const float* ar = sm + OFF_X + n * COLS_ + (bb0 + q) * S_;
#pragma unroll
                for (int d = 0; d < 10; ++d) {
                    pv[q][d] = pr[d];
                    av[q][d] = ar[d];
                }
            }
            // r and r*prop
#pragma unroll 2
            for (int s = 0; s < 10; ++s) {
                float r0 = sm[OFF_BR + s], r1 = r0;
#pragma unroll
                for (int j = 0; j < 10; ++j) {
                    float w = sm[OFF_WR + s * 20 + j];
                    r0 += av[0][j] * w;
                    r1 += av[1][j] * w;
                }
#pragma unroll
                for (int j = 0; j < 10; ++j) {
                    float w = sm[OFF_WR + s * 20 + 10 + j];
                    r0 += pv[0][j] * w;
                    r1 += pv[1][j] * w;
                }
                rp[0][s] = sigf(r0) * pv[0][s];
                rp[1][s] = sigf(r1) * pv[1][s];
            }
            // z, h_hat, update
#pragma unroll 2
            for (int s = 0; s < 10; ++s) {
                float z0 = sm[OFF_BZ + s], z1 = z0;
                float h0 = sm[OFF_BH + s], h1 = h0;
#pragma unroll
                for (int j = 0; j < 10; ++j) {
                    float wz = sm[OFF_WZ + s * 20 + j];
                    float wh = sm[OFF_WH + s * 20 + j];
                    z0 += av[0][j] * wz;
                    z1 += av[1][j] * wz;
                    h0 += av[0][j] * wh;
                    h1 += av[1][j] * wh;
                }
#pragma unroll
                for (int j = 0; j < 10; ++j) {
                    float wz = sm[OFF_WZ + s * 20 + 10 + j];
                    float wh = sm[OFF_WH + s * 20 + 10 + j];
                    z0 += pv[0][j] * wz;
                    z1 += pv[1][j] * wz;
                    h0 += rp[0][j] * wh;
                    h1 += rp[1][j] * wh;
                }
                z0 = sigf(z0); z1 = sigf(z1);
                h0 = tanh_(h0); h1 = tanh_(h1);
                sm[OFF_P + ((bb0 + 0) * N_ + n) * PSTR_ + s] =
                    pv[0][s] + z0 * (h0 - pv[0][s]);
                sm[OFF_P + ((bb0 + 1) * N_ + n) * PSTR_ + s] =
                    pv[1][s] + z1 * (h1 - pv[1][s]);
            }
        }
        __syncthreads();
    }

    // ---- output: out = tanh([prop, ann] @ Wo1^T + bo1) @ Wo2^T + bo2 ----
#pragma unroll 1
    for (int task = t; task < 8 * N_; task += TPB) {
        int n = task >> 3;
        int bb0 = (task & 7) * 2;
#pragma unroll
        for (int q = 0; q < 2; ++q) {
            int bb = bb0 + q;
            const float* pr = sm + OFF_P + (bb * N_ + n) * PSTR_;
            float an = sm[OFF_ANN + bb * N_ + n];
            float o = sm[OFF_BO2];
#pragma unroll 2
            for (int s = 0; s < 10; ++s) {
                float a0 = sm[OFF_BO1 + s];
#pragma unroll
                for (int j = 0; j < 10; ++j)
                    a0 += pr[j] * sm[OFF_WO1 + s * 11 + j];
                a0 += an * sm[OFF_WO1 + s * 11 + 10];
                o += tanh_(a0) * sm[OFF_WO2 + s];
            }
            out[(b0 + bb) * N_ + n] = o;
        }
    }
}

extern "C" void kernel_launch(void* const* d_in, const int* in_sizes, int n_in,
                              void* d_out, int out_size) {
    const float* annotation = (const float*)d_in[0];
    const float* A    = (const float*)d_in[1];
    const float* W_in = (const float*)d_in[2];
    const float* b_in = (const float*)d_in[3];
    const float* Wr   = (const float*)d_in[4];
    const float* br   = (const float*)d_in[5];
    const float* Wz   = (const float*)d_in[6];
    const float* bz   = (const float*)d_in[7];
    const float* Wh   = (const float*)d_in[8];
    const float* bh   = (const float*)d_in[9];
    const float* Wo1  = (const float*)d_in[10];
    const float* bo1  = (const float*)d_in[11];
    const float* Wo2  = (const float*)d_in[12];
    const float* bo2  = (const float*)d_in[13];
    float* out = (float*)d_out;

    const int smem_bytes = SMEM_FLOATS * (int)sizeof(float);
    cudaFuncSetAttribute(ggnn_kernel,
                         cudaFuncAttributeMaxDynamicSharedMemorySize, smem_bytes);
    ggnn_kernel<<<B_ / BB_, TPB, smem_bytes>>>(
        annotation, A, W_in, b_in, Wr, br, Wz, bz, Wh, bh,
        Wo1, bo1, Wo2, bo2, out);
}

// round 2
// speedup vs baseline: 1.0347x; 1.0347x over previous
#include <cuda_runtime.h>

#define TPB 256

constexpr int B_     = 16384;
constexpr int N_     = 70;
constexpr int E_     = 3;
constexpr int S_     = 10;
constexpr int STEPS_ = 5;
constexpr int BB_    = 16;            // batch elements per CTA
constexpr int COLS_  = BB_ * S_;      // 160 scalar columns
constexpr int PAIRS_ = COLS_ / 2;     // 80 f32x2 columns
constexpr int PSTR_  = 11;            // padded prop row stride

// ---- shared memory layout (float offsets) ----
constexpr int OFF_X    = 0;                        // 70*160 = 11200
constexpr int OFF_P    = OFF_X + N_ * COLS_;       // 16*70*11 = 12320
constexpr int OFF_ANN  = OFF_P + BB_ * N_ * PSTR_; // 1120
constexpr int OFF_WIN2 = OFF_ANN + BB_ * N_;       // 150 f2 = 300 fl  [e][d][s2]
constexpr int OFF_BIN2 = OFF_WIN2 + 300;           // 15 f2 = 30      [e][s2]
constexpr int OFF_WR2  = OFF_BIN2 + 30;            // 100 f2 = 200    [j][s2]
constexpr int OFF_BR2  = OFF_WR2 + 200;            // 5 f2 = 10
constexpr int OFF_WZ2  = OFF_BR2 + 10;             // 200
constexpr int OFF_BZ2  = OFF_WZ2 + 200;            // 10
constexpr int OFF_WH2  = OFF_BZ2 + 10;             // 200
constexpr int OFF_BH2  = OFF_WH2 + 200;            // 10
constexpr int OFF_WO1  = OFF_BH2 + 10;             // 110
constexpr int OFF_BO1  = OFF_WO1 + 110;            // 10
constexpr int OFF_WO2  = OFF_BO1 + 10;             // 10
constexpr int OFF_BO2  = OFF_WO2 + 10;             // 1
constexpr int SMEM_FLOATS = OFF_BO2 + 1;           // 25731 -> 102924 B

typedef unsigned long long u64;

// A duplicated as (a,a) float2 pairs; +2 pad elems for prefetch overread.
__device__ float2 g_Adup[N_ * E_ * N_ + 2];

__global__ void prep_kernel(const float* __restrict__ A) {
    int i = blockIdx.x * 256 + threadIdx.x;
    if (i < N_ * E_ * N_) {
        float v = A[i];
        g_Adup[i] = make_float2(v, v);
    } else if (i < N_ * E_ * N_ + 2) {
        g_Adup[i] = make_float2(0.0f, 0.0f);
    }
}

// ---- packed f32x2 helpers ----
__device__ __forceinline__ u64 ffma2(u64 a, u64 b, u64 c) {
    u64 d;
    asm("fma.rn.f32x2 %0, %1, %2, %3;" : "=l"(d) : "l"(a), "l"(b), "l"(c));
    return d;
}
__device__ __forceinline__ u64 pack2(float x) {
    u64 d;
    asm("mov.b64 %0, {%1, %1};" : "=l"(d) : "f"(x));
    return d;
}
__device__ __forceinline__ void unpack2(u64 v, float& x, float& y) {
    asm("mov.b64 {%0, %1}, %2;" : "=f"(x), "=f"(y) : "l"(v));
}

__device__ __forceinline__ float sigf(float x) {
    return __fdividef(1.0f, 1.0f + __expf(-x));
}
__device__ __forceinline__ float tanh_(float x) {
    float e = __expf(-2.0f * x);
    return __fdividef(1.0f - e, 1.0f + e);
}

extern __shared__ float sm[];

// R rows x 5 f32x2-column GEMM slice against X in smem; A from gmem (L2),
// distance-1 prefetch.
template <int R>
__device__ __forceinline__ void gemm_acc(u64 (&acc)[5][5],
                                         const float2* __restrict__ a0,
                                         const float2* __restrict__ a1,
                                         const float2* __restrict__ a2,
                                         const float2* __restrict__ a3,
                                         const float2* __restrict__ a4,
                                         const float* __restrict__ xs, int tx) {
    const u64* x2 = (const u64*)xs;
    const float2* ar[5] = {a0, a1, a2, a3, a4};
    u64 an[5];
#pragma unroll
    for (int i = 0; i < R; ++i) an[i] = *(const u64*)(ar[i]);
#pragma unroll 2
    for (int k = 0; k < 70; ++k) {
        u64 av[5], xv[5];
#pragma unroll
        for (int i = 0; i < R; ++i) av[i] = an[i];
#pragma unroll
        for (int i = 0; i < R; ++i) an[i] = *(const u64*)(ar[i] + k + 1);
#pragma unroll
        for (int j = 0; j < 5; ++j) xv[j] = x2[k * PAIRS_ + tx + 16 * j];
#pragma unroll
        for (int i = 0; i < R; ++i)
#pragma unroll
            for (int j = 0; j < 5; ++j)
                acc[i][j] = ffma2(av[i], xv[j], acc[i][j]);
    }
}

__global__ void __launch_bounds__(TPB, 2) ggnn_kernel(
    const float* __restrict__ annotation,
    const float* __restrict__ W_in, const float* __restrict__ b_in,
    const float* __restrict__ Wr, const float* __restrict__ br,
    const float* __restrict__ Wz, const float* __restrict__ bz,
    const float* __restrict__ Wh, const float* __restrict__ bh,
    const float* __restrict__ Wo1, const float* __restrict__ bo1,
    const float* __restrict__ Wo2, const float* __restrict__ bo2,
    float* __restrict__ out)
{
    const int t  = threadIdx.x;
    const int b0 = blockIdx.x * BB_;

    // ---- stage paired weight tables ----
    for (int i = t; i < 150; i += TPB) {     // WIN2 [e][d][s2]
        int s2 = i % 5, d = (i / 5) % 10, e = i / 50;
        ((float2*)(sm + OFF_WIN2))[i] =
            make_float2(W_in[(e * 10 + 2 * s2) * 10 + d],
                        W_in[(e * 10 + 2 * s2 + 1) * 10 + d]);
    }
    if (t < 15) {                            // BIN2 [e][s2]
        int s2 = t % 5, e = t / 5;
        ((float2*)(sm + OFF_BIN2))[t] =
            make_float2(b_in[e * 10 + 2 * s2], b_in[e * 10 + 2 * s2 + 1]);
    }
    for (int i = t; i < 100; i += TPB) {     // W{r,z,h}2 [j][s2]
        int s2 = i % 5, j = i / 5;
        ((float2*)(sm + OFF_WR2))[i] =
            make_float2(Wr[2 * s2 * 20 + j], Wr[(2 * s2 + 1) * 20 + j]);
        ((float2*)(sm + OFF_WZ2))[i] =
            make_float2(Wz[2 * s2 * 20 + j], Wz[(2 * s2 + 1) * 20 + j]);
        ((float2*)(sm + OFF_WH2))[i] =
            make_float2(Wh[2 * s2 * 20 + j], Wh[(2 * s2 + 1) * 20 + j]);
    }
    if (t < 5) {
        ((float2*)(sm + OFF_BR2))[t] = make_float2(br[2 * t], br[2 * t + 1]);
        ((float2*)(sm + OFF_BZ2))[t] = make_float2(bz[2 * t], bz[2 * t + 1]);
        ((float2*)(sm + OFF_BH2))[t] = make_float2(bh[2 * t], bh[2 * t + 1]);
    }
    for (int i = t; i < 110; i += TPB) sm[OFF_WO1 + i] = Wo1[i];
    if (t < 10) { sm[OFF_BO1 + t] = bo1[t]; sm[OFF_WO2 + t] = Wo2[t]; }
    if (t == 0) sm[OFF_BO2] = bo2[0];

    // ---- annotation + prop init ----
    for (int i = t; i < BB_ * N_; i += TPB) {
        int bb = i / N_, n = i % N_;
        float a = annotation[(b0 + bb) * N_ + n];
        sm[OFF_ANN + i] = a;
        float* pr = sm + OFF_P + (bb * N_ + n) * PSTR_;
        pr[0] = a;
#pragma unroll
        for (int d = 1; d < S_; ++d) pr[d] = 0.0f;
    }
    __syncthreads();

    const int tx = t & 15;   // f32x2 column group
    const int ty = t >> 4;   // row group
    const bool has5 = (ty < 6);

    u64 acc[5][5];

#pragma unroll 1
    for (int step = 0; step < STEPS_; ++step) {
#pragma unroll
        for (int i = 0; i < 5; ++i)
#pragma unroll
            for (int j = 0; j < 5; ++j) acc[i][j] = 0ull;

#pragma unroll 1
        for (int e = 0; e < E_; ++e) {
            // ---- build X[n, bb*10+s] = prop @ W_in[e]^T + b (s-paired f32x2) ----
#pragma unroll 1
            for (int task = t; task < 8 * N_; task += TPB) {
                int n = task >> 3;
                int bb0 = (task & 7) * 2;
                float pv0[10], pv1[10];
                const float* pr0 = sm + OFF_P + ((bb0 + 0) * N_ + n) * PSTR_;
                const float* pr1 = sm + OFF_P + ((bb0 + 1) * N_ + n) * PSTR_;
#pragma unroll
                for (int d = 0; d < 10; ++d) { pv0[d] = pr0[d]; pv1[d] = pr1[d]; }
                u64 a2[2][5];
                const u64* B2 = (const u64*)(sm + OFF_BIN2) + e * 5;
#pragma unroll
                for (int s2 = 0; s2 < 5; ++s2) {
                    u64 b = B2[s2];
                    a2[0][s2] = b; a2[1][s2] = b;
                }
                const u64* W2 = (const u64*)(sm + OFF_WIN2) + e * 50;
#pragma unroll
                for (int d = 0; d < 10; ++d) {
                    u64 p0 = pack2(pv0[d]), p1 = pack2(pv1[d]);
#pragma unroll
                    for (int s2 = 0; s2 < 5; ++s2) {
                        u64 w = W2[d * 5 + s2];
                        a2[0][s2] = ffma2(p0, w, a2[0][s2]);
                        a2[1][s2] = ffma2(p1, w, a2[1][s2]);
                    }
                }
#pragma unroll
                for (int q = 0; q < 2; ++q)
#pragma unroll
                    for (int s2 = 0; s2 < 5; ++s2)
                        *(u64*)(sm + OFF_X + n * COLS_ + (bb0 + q) * S_ + 2 * s2)
                            = a2[q][s2];
            }
            __syncthreads();

            // ---- acc += A[:, e*70:(e+1)*70] @ X ----
            {
                const float2* a0 = g_Adup + (ty +  0) * 210 + e * 70;
                const float2* a1 = g_Adup + (ty + 16) * 210 + e * 70;
                const float2* a2p = g_Adup + (ty + 32) * 210 + e * 70;
                const float2* a3 = g_Adup + (ty + 48) * 210 + e * 70;
                const float2* a4 = g_Adup + (64 + ty) * 210 + e * 70;
                if (has5)
                    gemm_acc<5>(acc, a0, a1, a2p, a3, a4, sm + OFF_X, tx);
                else
                    gemm_acc<4>(acc, a0, a1, a2p, a3, a4, sm + OFF_X, tx);
            }
            __syncthreads();
        }

        // ---- write a_in into X buffer ----
#pragma unroll
        for (int i = 0; i < 4; ++i) {
            int n = ty + 16 * i;
#pragma unroll
            for (int j = 0; j < 5; ++j)
                *(u64*)(sm + OFF_X + n * COLS_ + 2 * (tx + 16 * j)) = acc[i][j];
        }
        if (has5) {
            int n = 64 + ty;
#pragma unroll
            for (int j = 0; j < 5; ++j)
                *(u64*)(sm + OFF_X + n * COLS_ + 2 * (tx + 16 * j)) = acc[4][j];
        }
        __syncthreads();

        // ---- gates (single-batch tasks, s-paired f32x2) ----
#pragma unroll 1
        for (int task = t; task < BB_ * N_; task += TPB) {
            int bb = task & 15, n = task >> 4;
            float* pr = sm + OFF_P + (bb * N_ + n) * PSTR_;
            const float* ain = sm + OFF_X + n * COLS_ + bb * S_;
            float av[10], pv[10];
#pragma unroll
            for (int d = 0; d < 10; ++d) { av[d] = ain[d]; pv[d] = pr[d]; }

            const u64* WRp = (const u64*)(sm + OFF_WR2);
            const u64* WZp = (const u64*)(sm + OFF_WZ2);
            const u64* WHp = (const u64*)(sm + OFF_WH2);

            u64 accr[5];
#pragma unroll
            for (int s2 = 0; s2 < 5; ++s2)
                accr[s2] = ((const u64*)(sm + OFF_BR2))[s2];
#pragma unroll
            for (int j = 0; j < 20; ++j) {
                u64 o = pack2(j < 10 ? av[j] : pv[j - 10]);
#pragma unroll
                for (int s2 = 0; s2 < 5; ++s2)
                    accr[s2] = ffma2(o, WRp[j * 5 + s2], accr[s2]);
            }
            float rp[10];
#pragma unroll
            for (int s2 = 0; s2 < 5; ++s2) {
                float x, y; unpack2(accr[s2], x, y);
                rp[2 * s2]     = sigf(x) * pv[2 * s2];
                rp[2 * s2 + 1] = sigf(y) * pv[2 * s2 + 1];
            }
            u64 accz[5], acch[5];
#pragma unroll
            for (int s2 = 0; s2 < 5; ++s2) {
                accz[s2] = ((const u64*)(sm + OFF_BZ2))[s2];
                acch[s2] = ((const u64*)(sm + OFF_BH2))[s2];
            }
#pragma unroll
            for (int j = 0; j < 20; ++j) {
                u64 oz = pack2(j < 10 ? av[j] : pv[j - 10]);
                u64 oh = (j < 10) ? oz : pack2(rp[j - 10]);
#pragma unroll
                for (int s2 = 0; s2 < 5; ++s2) {
                    accz[s2] = ffma2(oz, WZp[j * 5 + s2], accz[s2]);
                    acch[s2] = ffma2(oh, WHp[j * 5 + s2], acch[s2]);
                }
            }
#pragma unroll
            for (int s2 = 0; s2 < 5; ++s2) {
                float zx, zy, hx, hy;
                unpack2(accz[s2], zx, zy);
                unpack2(acch[s2], hx, hy);
                zx = sigf(zx); zy = sigf(zy);
                hx = tanh_(hx); hy = tanh_(hy);
                pr[2 * s2]     = pv[2 * s2]     + zx * (hx - pv[2 * s2]);
                pr[2 * s2 + 1] = pv[2 * s2 + 1] + zy * (hy - pv[2 * s2 + 1]);
            }
        }
        __syncthreads();
    }

    // ---- output ----
#pragma unroll 1
    for (int task = t; task < BB_ * N_; task += TPB) {
        int n = task % N_, bb = task / N_;
        const float* pr = sm + OFF_P + (bb * N_ + n) * PSTR_;
        float an = sm[OFF_ANN + bb * N_ + n];
        float o = sm[OFF_BO2];
#pragma unroll 2
        for (int s = 0; s < 10; ++s) {
            float a0 = sm[OFF_BO1 + s];
#pragma unroll
            for (int j = 0; j < 10; ++j)
                a0 += pr[j] * sm[OFF_WO1 + s * 11 + j];
            a0 += an * sm[OFF_WO1 + s * 11 + 10];
            o += tanh_(a0) * sm[OFF_WO2 + s];
        }
        out[(b0 + bb) * N_ + n] = o;
    }
}

extern "C" void kernel_launch(void* const* d_in, const int* in_sizes, int n_in,
                              void* d_out, int out_size) {
    const float* annotation = (const float*)d_in[0];
    const float* A    = (const float*)d_in[1];
    const float* W_in = (const float*)d_in[2];
    const float* b_in = (const float*)d_in[3];
    const float* Wr   = (const float*)d_in[4];
    const float* br   = (const float*)d_in[5];
    const float* Wz   = (const float*)d_in[6];
    const float* bz   = (const float*)d_in[7];
    const float* Wh   = (const float*)d_in[8];
    const float* bh   = (const float*)d_in[9];
    const float* Wo1  = (const float*)d_in[10];
    const float* bo1  = (const float*)d_in[11];
    const float* Wo2  = (const float*)d_in[12];
    const float* bo2  = (const float*)d_in[13];
    float* out = (float*)d_out;

    prep_kernel<<<(N_ * E_ * N_ + 2 + 255) / 256, 256>>>(A);

    const int smem_bytes = SMEM_FLOATS * (int)sizeof(float);
    cudaFuncSetAttribute(ggnn_kernel,
                         cudaFuncAttributeMaxDynamicSharedMemorySize, smem_bytes);
    ggnn_kernel<<<B_ / BB_, TPB, smem_bytes>>>(
        annotation, W_in, b_in, Wr, br, Wz, bz, Wh, bh,
        Wo1, bo1, Wo2, bo2, out);
}

// round 3
// speedup vs baseline: 1.1545x; 1.1158x over previous
#include <cuda_runtime.h>

#define TPB 256

constexpr int B_     = 16384;
constexpr int N_     = 70;
constexpr int E_     = 3;
constexpr int S_     = 10;
constexpr int STEPS_ = 5;
constexpr int BB_    = 16;            // batch elements per CTA
constexpr int COLS_  = BB_ * S_;      // 160 scalar columns
constexpr int PAIRS_ = COLS_ / 2;     // 80 f32x2 columns

// ---- shared memory layout (float offsets) ----
constexpr int OFF_X    = 0;                      // 70*160 = 11200
constexpr int OFF_P    = OFF_X + N_ * COLS_;     // s-planes: 10*1120 = 11200
constexpr int OFF_AS   = OFF_P + 10 * 1120;      // A chunk 70*70 = 4900
constexpr int OFF_WIN2 = OFF_AS + 4900;          // [e][d][6] u64 = 360 fl (27300)
constexpr int OFF_BIN2 = OFF_WIN2 + 360;         // 15 u64 = 30 fl (27660)
constexpr int OFF_WR2  = 27692;                  // [j][6] u64 = 240 fl
constexpr int OFF_BR2  = OFF_WR2 + 240;          // 27932
constexpr int OFF_WZ2  = 27944;                  // 240
constexpr int OFF_BZ2  = OFF_WZ2 + 240;          // 28184
constexpr int OFF_WH2  = 28196;                  // 240
constexpr int OFF_BH2  = OFF_WH2 + 240;          // 28436
constexpr int OFF_WO1  = OFF_BH2 + 10;           // 28446, 110
constexpr int OFF_BO1  = OFF_WO1 + 110;          // 10
constexpr int OFF_WO2  = OFF_BO1 + 10;           // 10
constexpr int OFF_BO2  = OFF_WO2 + 10;           // 1
constexpr int SMEM_FLOATS = OFF_BO2 + 1;         // 28577 -> 114308 B/CTA

typedef unsigned long long u64;

// ---- packed f32x2 helpers ----
__device__ __forceinline__ u64 ffma2(u64 a, u64 b, u64 c) {
    u64 d;
    asm("fma.rn.f32x2 %0, %1, %2, %3;" : "=l"(d) : "l"(a), "l"(b), "l"(c));
    return d;
}
__device__ __forceinline__ u64 pack2(float x) {
    u64 d;
    asm("mov.b64 %0, {%1, %1};" : "=l"(d) : "f"(x));
    return d;
}
__device__ __forceinline__ void unpack2(u64 v, float& x, float& y) {
    asm("mov.b64 {%0, %1}, %2;" : "=f"(x), "=f"(y) : "l"(v));
}

__device__ __forceinline__ float sigf(float x) {
    return __fdividef(1.0f, 1.0f + __expf(-x));
}
__device__ __forceinline__ float tanh_(float x) {
    float e = __expf(-2.0f * x);
    return __fdividef(1.0f - e, 1.0f + e);
}

extern __shared__ float sm[];

__global__ void __launch_bounds__(TPB, 2) ggnn_kernel(
    const float* __restrict__ annotation, const float* __restrict__ Ag,
    const float* __restrict__ W_in, const float* __restrict__ b_in,
    const float* __restrict__ Wr, const float* __restrict__ br,
    const float* __restrict__ Wz, const float* __restrict__ bz,
    const float* __restrict__ Wh, const float* __restrict__ bh,
    const float* __restrict__ Wo1, const float* __restrict__ bo1,
    const float* __restrict__ Wo2, const float* __restrict__ bo2,
    float* __restrict__ out)
{
    const int t  = threadIdx.x;
    const int b0 = blockIdx.x * BB_;

    // ---- stage paired weight tables ----
    for (int i = t; i < 150; i += TPB) {      // WIN2 [e][d][6] (s-pairs)
        int s2 = i % 5, d = (i / 5) % 10, e = i / 50;
        ((float2*)(sm + OFF_WIN2))[e * 60 + d * 6 + s2] =
            make_float2(W_in[(e * 10 + 2 * s2) * 10 + d],
                        W_in[(e * 10 + 2 * s2 + 1) * 10 + d]);
    }
    if (t < 15) {                             // BIN2 [e][s2]
        int s2 = t % 5, e = t / 5;
        ((float2*)(sm + OFF_BIN2))[t] =
            make_float2(b_in[e * 10 + 2 * s2], b_in[e * 10 + 2 * s2 + 1]);
    }
    for (int i = t; i < 100; i += TPB) {      // W{r,z,h}2 [j][6] (s-pairs)
        int s2 = i % 5, j = i / 5;
        ((float2*)(sm + OFF_WR2))[j * 6 + s2] =
            make_float2(Wr[2 * s2 * 20 + j], Wr[(2 * s2 + 1) * 20 + j]);
        ((float2*)(sm + OFF_WZ2))[j * 6 + s2] =
            make_float2(Wz[2 * s2 * 20 + j], Wz[(2 * s2 + 1) * 20 + j]);
        ((float2*)(sm + OFF_WH2))[j * 6 + s2] =
            make_float2(Wh[2 * s2 * 20 + j], Wh[(2 * s2 + 1) * 20 + j]);
    }
    if (t < 5) {
        ((float2*)(sm + OFF_BR2))[t] = make_float2(br[2 * t], br[2 * t + 1]);
        ((float2*)(sm + OFF_BZ2))[t] = make_float2(bz[2 * t], bz[2 * t + 1]);
        ((float2*)(sm + OFF_BH2))[t] = make_float2(bh[2 * t], bh[2 * t + 1]);
    }
    for (int i = t; i < 110; i += TPB) sm[OFF_WO1 + i] = Wo1[i];
    if (t < 10) { sm[OFF_BO1 + t] = bo1[t]; sm[OFF_WO2 + t] = Wo2[t]; }
    if (t == 0) sm[OFF_BO2] = bo2[0];

    // ---- prop init: P[0][idx] = ann, P[1..9][idx] = 0 ----
    for (int i = t; i < BB_ * N_; i += TPB) {
        float a = annotation[b0 * N_ + i];
        sm[OFF_P + i] = a;
#pragma unroll
        for (int d = 1; d < S_; ++d) sm[OFF_P + d * 1120 + i] = 0.0f;
    }
    __syncthreads();

    const int tx = t & 15;   // f32x2 column group
    const int ty = t >> 4;   // row group
    const bool has5 = (ty < 6);
    const int r4 = has5 ? (64 + ty) * 35 : 0;   // u64-index row base

    u64 acc[5][5];

#pragma unroll 1
    for (int step = 0; step < STEPS_; ++step) {
#pragma unroll
        for (int i = 0; i < 5; ++i)
#pragma unroll
            for (int j = 0; j < 5; ++j) acc[i][j] = 0ull;

#pragma unroll 1
        for (int e = 0; e < E_; ++e) {
            // ---- stage A[:, e*70:(e+1)*70] into SMEM (float2 granules) ----
            {
                const float2* Ag2 = (const float2*)Ag;
                float2* As2 = (float2*)(sm + OFF_AS);
#pragma unroll 1
                for (int i = t; i < 2450; i += TPB) {
                    int row = i / 35, kk = i - row * 35;
                    As2[i] = Ag2[row * 105 + e * 35 + kk];
                }
            }
            // ---- build X[n][bb*10+s] = prop @ W_in[e]^T + b (register-light) ----
#pragma unroll 1
            for (int task = t; task < BB_ * N_; task += TPB) {
                int bb = task & 15, n = task >> 4;
                int idx = bb * N_ + n;
                const u64* B2 = (const u64*)(sm + OFF_BIN2) + e * 5;
                u64 a0 = B2[0], a1 = B2[1], a2 = B2[2], a3 = B2[3], a4 = B2[4];
                const float* Wb = sm + OFF_WIN2 + e * 120;
#pragma unroll
                for (int d = 0; d < 10; ++d) {
                    u64 p2 = pack2(sm[OFF_P + d * 1120 + idx]);
                    ulonglong2 wa = *(const ulonglong2*)(Wb + d * 12);
                    ulonglong2 wb = *(const ulonglong2*)(Wb + d * 12 + 4);
                    u64 wc = *(const u64*)(Wb + d * 12 + 8);
                    a0 = ffma2(p2, wa.x, a0);
                    a1 = ffma2(p2, wa.y, a1);
                    a2 = ffma2(p2, wb.x, a2);
                    a3 = ffma2(p2, wb.y, a3);
                    a4 = ffma2(p2, wc, a4);
                }
                u64* xo = (u64*)(sm + OFF_X + n * COLS_ + bb * S_);
                xo[0] = a0; xo[1] = a1; xo[2] = a2; xo[3] = a3; xo[4] = a4;
            }
            __syncthreads();

            // ---- acc += A_chunk @ X (A from SMEM, 2 k per iter) ----
            {
                const u64* As2 = (const u64*)(sm + OFF_AS);
                const u64* Xb  = (const u64*)(sm + OFF_X);
                const int r0 = ty * 35;
#pragma unroll 1
                for (int k2 = 0; k2 < 35; ++k2) {
                    const u64* x0 = Xb + (2 * k2) * PAIRS_ + tx;
                    u64 xE[5], xO[5];
#pragma unroll
                    for (int j = 0; j < 5; ++j) {
                        xE[j] = x0[16 * j];
                        xO[j] = x0[PAIRS_ + 16 * j];
                    }
#pragma unroll
                    for (int i = 0; i < 4; ++i) {
                        u64 aw = As2[r0 + i * (16 * 35) + k2];
                        float lo, hi; unpack2(aw, lo, hi);
                        u64 aE = pack2(lo), aO = pack2(hi);
#pragma unroll
                        for (int j = 0; j < 5; ++j) {
                            acc[i][j] = ffma2(aE, xE[j], acc[i][j]);
                            acc[i][j] = ffma2(aO, xO[j], acc[i][j]);
                        }
                    }
                    if (has5) {
                        u64 aw = As2[r4 + k2];
                        float lo, hi; unpack2(aw, lo, hi);
                        u64 aE = pack2(lo), aO = pack2(hi);
#pragma unroll
                        for (int j = 0; j < 5; ++j) {
                            acc[4][j] = ffma2(aE, xE[j], acc[4][j]);
                            acc[4][j] = ffma2(aO, xO[j], acc[4][j]);
                        }
                    }
                }
            }
            __syncthreads();
        }

        // ---- write a_in into X buffer ----
#pragma unroll
        for (int i = 0; i < 4; ++i) {
            int n = ty + 16 * i;
#pragma unroll
            for (int j = 0; j < 5; ++j)
                *(u64*)(sm + OFF_X + n * COLS_ + 2 * (tx + 16 * j)) = acc[i][j];
        }
        if (has5) {
            int n = 64 + ty;
#pragma unroll
            for (int j = 0; j < 5; ++j)
                *(u64*)(sm + OFF_X + n * COLS_ + 2 * (tx + 16 * j)) = acc[4][j];
        }
        __syncthreads();

        // ---- gates: 2 batch elements per task, shared W broadcasts ----
#pragma unroll 1
        for (int task = t; task < 8 * N_; task += TPB) {
            int bb0 = (task & 7) * 2, n = task >> 3;
            int idx0 = bb0 * N_ + n, idx1 = idx0 + N_;
            float pv0[10], pv1[10], av0[10], av1[10];
#pragma unroll
            for (int d = 0; d < 10; ++d) {
                pv0[d] = sm[OFF_P + d * 1120 + idx0];
                pv1[d] = sm[OFF_P + d * 1120 + idx1];
            }
            {
                const u64* xr = (const u64*)(sm + OFF_X) + n * PAIRS_ + bb0 * 5;
#pragma unroll
                for (int s2 = 0; s2 < 5; ++s2) {
                    unpack2(xr[s2],     av0[2 * s2], av0[2 * s2 + 1]);
                    unpack2(xr[5 + s2], av1[2 * s2], av1[2 * s2 + 1]);
                }
            }
            // r gate
            u64 r0a[5], r1a[5];
#pragma unroll
            for (int s2 = 0; s2 < 5; ++s2) {
                u64 b = ((const u64*)(sm + OFF_BR2))[s2];
                r0a[s2] = b; r1a[s2] = b;
            }
            const float* WRb = sm + OFF_WR2;
#pragma unroll
            for (int j = 0; j < 20; ++j) {
                u64 o0 = pack2(j < 10 ? av0[j] : pv0[j - 10]);
                u64 o1 = pack2(j < 10 ? av1[j] : pv1[j - 10]);
                ulonglong2 wa = *(const ulonglong2*)(WRb + j * 12);
                ulonglong2 wb = *(const ulonglong2*)(WRb + j * 12 + 4);
                u64 wc = *(const u64*)(WRb + j * 12 + 8);
                r0a[0] = ffma2(o0, wa.x, r0a[0]); r1a[0] = ffma2(o1, wa.x, r1a[0]);
                r0a[1] = ffma2(o0, wa.y, r0a[1]); r1a[1] = ffma2(o1, wa.y, r1a[1]);
                r0a[2] = ffma2(o0, wb.x, r0a[2]); r1a[2] = ffma2(o1, wb.x, r1a[2]);
                r0a[3] = ffma2(o0, wb.y, r0a[3]); r1a[3] = ffma2(o1, wb.y, r1a[3]);
                r0a[4] = ffma2(o0, wc,   r0a[4]); r1a[4] = ffma2(o1, wc,   r1a[4]);
            }
            float rp0[10], rp1[10];
#pragma unroll
            for (int s2 = 0; s2 < 5; ++s2) {
                float x, y;
                unpack2(r0a[s2], x, y);
                rp0[2 * s2] = sigf(x) * pv0[2 * s2];
                rp0[2 * s2 + 1] = sigf(y) * pv0[2 * s2 + 1];
                unpack2(r1a[s2], x, y);
                rp1[2 * s2] = sigf(x) * pv1[2 * s2];
                rp1[2 * s2 + 1] = sigf(y) * pv1[2 * s2 + 1];
            }
            // z and h_hat
            u64 z0a[5], z1a[5], h0a[5], h1a[5];
#pragma unroll
            for (int s2 = 0; s2 < 5; ++s2) {
                u64 bz2 = ((const u64*)(sm + OFF_BZ2))[s2];
                u64 bh2 = ((const u64*)(sm + OFF_BH2))[s2];
                z0a[s2] = bz2; z1a[s2] = bz2;
                h0a[s2] = bh2; h1a[s2] = bh2;
            }
            const float* WZb = sm + OFF_WZ2;
            const float* WHb = sm + OFF_WH2;
#pragma unroll
            for (int j = 0; j < 20; ++j) {
                u64 o0 = pack2(j < 10 ? av0[j] : pv0[j - 10]);
                u64 o1 = pack2(j < 10 ? av1[j] : pv1[j - 10]);
                u64 q0 = (j < 10) ? o0 : pack2(rp0[j - 10]);
                u64 q1 = (j < 10) ? o1 : pack2(rp1[j - 10]);
                ulonglong2 za = *(const ulonglong2*)(WZb + j * 12);
                ulonglong2 zb = *(const ulonglong2*)(WZb + j * 12 + 4);
                u64 zc = *(const u64*)(WZb + j * 12 + 8);
                ulonglong2 ha = *(const ulonglong2*)(WHb + j * 12);
                ulonglong2 hb = *(const ulonglong2*)(WHb + j * 12 + 4);
                u64 hc = *(const u64*)(WHb + j * 12 + 8);
                z0a[0] = ffma2(o0, za.x, z0a[0]); z1a[0] = ffma2(o1, za.x, z1a[0]);
                z0a[1] = ffma2(o0, za.y, z0a[1]); z1a[1] = ffma2(o1, za.y, z1a[1]);
                z0a[2] = ffma2(o0, zb.x, z0a[2]); z1a[2] = ffma2(o1, zb.x, z1a[2]);
                z0a[3] = ffma2(o0, zb.y, z0a[3]); z1a[3] = ffma2(o1, zb.y, z1a[3]);
                z0a[4] = ffma2(o0, zc,   z0a[4]); z1a[4] = ffma2(o1, zc,   z1a[4]);
                h0a[0] = ffma2(q0, ha.x, h0a[0]); h1a[0] = ffma2(q1, ha.x, h1a[0]);
                h0a[1] = ffma2(q0, ha.y, h0a[1]); h1a[1] = ffma2(q1, ha.y, h1a[1]);
                h0a[2] = ffma2(q0, hb.x, h0a[2]); h1a[2] = ffma2(q1, hb.x, h1a[2]);
                h0a[3] = ffma2(q0, hb.y, h0a[3]); h1a[3] = ffma2(q1, hb.y, h1a[3]);
                h0a[4] = ffma2(q0, hc,   h0a[4]); h1a[4] = ffma2(q1, hc,   h1a[4]);
            }
#pragma unroll
            for (int s2 = 0; s2 < 5; ++s2) {
                float zx, zy, hx, hy;
                unpack2(z0a[s2], zx, zy);
                unpack2(h0a[s2], hx, hy);
                zx = sigf(zx); zy = sigf(zy);
                hx = tanh_(hx); hy = tanh_(hy);
                sm[OFF_P + (2 * s2) * 1120 + idx0] =
                    pv0[2 * s2] + zx * (hx - pv0[2 * s2]);
                sm[OFF_P + (2 * s2 + 1) * 1120 + idx0] =
                    pv0[2 * s2 + 1] + zy * (hy - pv0[2 * s2 + 1]);
                unpack2(z1a[s2], zx, zy);
                unpack2(h1a[s2], hx, hy);
                zx = sigf(zx); zy = sigf(zy);
                hx = tanh_(hx); hy = tanh_(hy);
                sm[OFF_P + (2 * s2) * 1120 + idx1] =
                    pv1[2 * s2] + zx * (hx - pv1[2 * s2]);
                sm[OFF_P + (2 * s2 + 1) * 1120 + idx1] =
                    pv1[2 * s2 + 1] + zy * (hy - pv1[2 * s2 + 1]);
            }
        }
        __syncthreads();
    }

    // ---- output ----
#pragma unroll 1
    for (int task = t; task < BB_ * N_; task += TPB) {
        int bb = task / N_, n = task - bb * N_;
        int idx = bb * N_ + n;
        float an = annotation[b0 * N_ + idx];
        float o = sm[OFF_BO2];
#pragma unroll 2
        for (int s = 0; s < 10; ++s) {
            float a0 = sm[OFF_BO1 + s];
#pragma unroll
            for (int j = 0; j < 10; ++j)
                a0 += sm[OFF_P + j * 1120 + idx] * sm[OFF_WO1 + s * 11 + j];
            a0 += an * sm[OFF_WO1 + s * 11 + 10];
            o += tanh_(a0) * sm[OFF_WO2 + s];
        }
        out[b0 * N_ + idx] = o;
    }
}

extern "C" void kernel_launch(void* const* d_in, const int* in_sizes, int n_in,
                              void* d_out, int out_size) {
    const float* annotation = (const float*)d_in[0];
    const float* A    = (const float*)d_in[1];
    const float* W_in = (const float*)d_in[2];
    const float* b_in = (const float*)d_in[3];
    const float* Wr   = (const float*)d_in[4];
    const float* br   = (const float*)d_in[5];
    const float* Wz   = (const float*)d_in[6];
    const float* bz   = (const float*)d_in[7];
    const float* Wh   = (const float*)d_in[8];
    const float* bh   = (const float*)d_in[9];
    const float* Wo1  = (const float*)d_in[10];
    const float* bo1  = (const float*)d_in[11];
    const float* Wo2  = (const float*)d_in[12];
    const float* bo2  = (const float*)d_in[13];
    float* out = (float*)d_out;

    const int smem_bytes = SMEM_FLOATS * (int)sizeof(float);
    cudaFuncSetAttribute(ggnn_kernel,
                         cudaFuncAttributeMaxDynamicSharedMemorySize, smem_bytes);
    ggnn_kernel<<<B_ / BB_, TPB, smem_bytes>>>(
        annotation, A, W_in, b_in, Wr, br, Wz, bz, Wh, bh,
        Wo1, bo1, Wo2, bo2, out);
}